// round 11
// baseline (speedup 1.0000x reference)
#include <cuda_runtime.h>

#define B_  4
#define H_  256
#define W_  256
#define CIN 256
#define CM  64
#define HW  (H_*W_)

// ---------------- scratch (static device memory — no allocations) ----------------
__device__ float g_y[(size_t)B_*CM*HW];       // 64 MB: conv_in output
__device__ float g_edge[(size_t)B_*CM*HW];    // 64 MB: edge_raw (pre-normalization)
__device__ float g_wr[CIN*CM];                // w_in tf32-rounded [c][o]
__device__ float g_or[B_*CM*CM];              // folded out weights tf32-rounded [b][c][o]
__device__ float g_scale[B_*CM];              // sigmoid(..)*inv_max per (b,c)
__device__ float g_sums[B_*CM];               // per-(b,c) edge sums
__device__ unsigned int g_maxbits;            // global max (float bits, edge>=0)

// Separable gaussian taps (sigma=2, size=5)
static constexpr double GE0 = 0.6065306597126334;
static constexpr double GE1 = 0.8824969025845955;
static constexpr double GSUM = 2.0*(GE0+GE1)+1.0;
static constexpr float G0 = (float)(GE0/GSUM);
static constexpr float G1 = (float)(GE1/GSUM);
static constexpr float G2 = (float)(1.0/GSUM);

// ---------------- tf32 / async helpers ----------------
__device__ __forceinline__ float tf32_big(float x) {
    unsigned r;
    asm("cvt.rna.tf32.f32 %0, %1;" : "=r"(r) : "f"(x));
    return __uint_as_float(r);
}
__device__ __forceinline__ unsigned tf32_bits(float x) {
    unsigned r;
    asm("cvt.rna.tf32.f32 %0, %1;" : "=r"(r) : "f"(x));
    return r;
}
__device__ __forceinline__ void mma8(float* c, const unsigned* a, unsigned b0, unsigned b1) {
    asm("mma.sync.aligned.m16n8k8.row.col.f32.tf32.tf32.f32 "
        "{%0,%1,%2,%3}, {%4,%5,%6,%7}, {%8,%9}, {%0,%1,%2,%3};"
        : "+f"(c[0]), "+f"(c[1]), "+f"(c[2]), "+f"(c[3])
        : "r"(a[0]), "r"(a[1]), "r"(a[2]), "r"(a[3]), "r"(b0), "r"(b1));
}
__device__ __forceinline__ void cp16(void* smem, const void* g) {
    unsigned s = (unsigned)__cvta_generic_to_shared(smem);
    asm volatile("cp.async.ca.shared.global [%0], [%1], 16;" :: "r"(s), "l"(g));
}
#define CP_COMMIT() asm volatile("cp.async.commit_group;" ::: "memory")
#define CP_WAIT0()  asm volatile("cp.async.wait_group 0;" ::: "memory")

// smem strides (floats); 264,72 == 8 mod 32 -> conflict-free frag LDS; 132 -> conflict-free STS
#define ASTR 264
#define BSTR 72
#define OSTR 132

struct alignas(16) GSmem {
    union {
        struct {
            float xr[2][16*ASTR];   // raw x chunk (16ch x 256px), double-buffered
            float wr[2][16*BSTR];   // tf32-rounded w chunk (16ch x 64out)
        } s;
        float outs[64*OSTR];        // epilogue staging (one 128-px phase)
    };
};

// ---------------- 1-term TF32 GEMM body: [KTOT ch] x [256 px] tile -> 64 outs ----------------
// 8 warps; warp w covers px [w*32, w*32+32), ALL 64 outs (mt=2, nt=8).
// CVT_A=false: feed raw fp32 bits as tf32 (HW conversion; numerically verified benign here).
template<int KTOT, bool CVT_A>
__device__ __forceinline__ void gemm_body(const float* __restrict__ xpx,
                                          const float* __restrict__ wrp,
                                          const float* __restrict__ bias,
                                          float* __restrict__ yout) {
    __shared__ GSmem sm;
    const int t = threadIdx.x;
    const int l = t & 31, wm = t >> 5;          // 8 warps = 8 px-groups of 32
    const int lr = l >> 2, lc = l & 3;

    float acc[2][8][4];
#pragma unroll
    for (int mt = 0; mt < 2; ++mt)
#pragma unroll
        for (int nt = 0; nt < 8; ++nt)
#pragma unroll
            for (int q = 0; q < 4; ++q) acc[mt][nt][q] = 0.f;

    // per-thread load indices
    const int xk0 = t >> 6,  xc0 = (t & 63) * 4;   // 4 rows of x per thread (rows xk0+4r)
    const int wk  = t >> 4,  wc  = (t & 15) * 4;

    // prologue: load chunk 0 into buf 0
    {
#pragma unroll
        for (int r = 0; r < 4; ++r)
            cp16(&sm.s.xr[0][(xk0 + 4*r)*ASTR + xc0], xpx + (size_t)(xk0 + 4*r)*HW + xc0);
        cp16(&sm.s.wr[0][wk*BSTR + wc], wrp + wk*CM + wc);
        CP_COMMIT();
    }

    int buf = 0;
    for (int kc = 0; kc < KTOT; kc += 16) {
        CP_WAIT0();
        __syncthreads();

        // issue next chunk into the other buffer (overlaps with MMA below)
        if (kc + 16 < KTOT) {
            int nb = buf ^ 1, kn = kc + 16;
#pragma unroll
            for (int r = 0; r < 4; ++r)
                cp16(&sm.s.xr[nb][(xk0 + 4*r)*ASTR + xc0], xpx + (size_t)(kn + xk0 + 4*r)*HW + xc0);
            cp16(&sm.s.wr[nb][wk*BSTR + wc], wrp + (kn + wk)*CM + wc);
            CP_COMMIT();
        }

        const float* __restrict__ xb = sm.s.xr[buf];
        const float* __restrict__ wb = sm.s.wr[buf];

#pragma unroll
        for (int k8 = 0; k8 < 16; k8 += 8) {
            const int kk = k8 + lc;
            unsigned A[2][4];
#pragma unroll
            for (int mt = 0; mt < 2; ++mt) {
                const int px = wm*32 + mt*16 + lr;
                if (CVT_A) {
                    A[mt][0] = tf32_bits(xb[kk*ASTR + px]);
                    A[mt][1] = tf32_bits(xb[kk*ASTR + px + 8]);
                    A[mt][2] = tf32_bits(xb[(kk+4)*ASTR + px]);
                    A[mt][3] = tf32_bits(xb[(kk+4)*ASTR + px + 8]);
                } else {
                    A[mt][0] = __float_as_uint(xb[kk*ASTR + px]);
                    A[mt][1] = __float_as_uint(xb[kk*ASTR + px + 8]);
                    A[mt][2] = __float_as_uint(xb[(kk+4)*ASTR + px]);
                    A[mt][3] = __float_as_uint(xb[(kk+4)*ASTR + px + 8]);
                }
            }
#pragma unroll
            for (int nt = 0; nt < 8; ++nt) {
                const int n = nt*8 + lr;
                unsigned B0 = __float_as_uint(wb[kk*BSTR + n]);
                unsigned B1 = __float_as_uint(wb[(kk+4)*BSTR + n]);
#pragma unroll
                for (int mt = 0; mt < 2; ++mt)
                    mma8(acc[mt][nt], A[mt], B0, B1);
            }
        }
        __syncthreads();
        buf ^= 1;
    }

    // epilogue: two 128-px phases (warps 0-3 then 4-7) staged via smem, coalesced out
#pragma unroll
    for (int phase = 0; phase < 2; ++phase) {
        if ((wm >> 2) == phase) {
#pragma unroll
            for (int mt = 0; mt < 2; ++mt) {
#pragma unroll
                for (int nt = 0; nt < 8; ++nt) {
                    int px = (wm & 3)*32 + mt*16 + lr;
                    int o  = nt*8 + 2*lc;
                    sm.outs[o*OSTR + px]           = acc[mt][nt][0];
                    sm.outs[(o+1)*OSTR + px]       = acc[mt][nt][1];
                    sm.outs[o*OSTR + px + 8]       = acc[mt][nt][2];
                    sm.outs[(o+1)*OSTR + px + 8]   = acc[mt][nt][3];
                }
            }
        }
        __syncthreads();
#pragma unroll
        for (int p = 0; p < 8; ++p) {
            int i = p*256 + t;
            int o = i >> 5, c4 = (i & 31) * 4;
            float4 v = *(const float4*)&sm.outs[o*OSTR + c4];
            float bv = bias[o];
            v.x += bv; v.y += bv; v.z += bv; v.w += bv;
            *(float4*)(yout + (size_t)o*HW + phase*128 + c4) = v;
        }
        __syncthreads();
    }
}

// ---------------- init: tf32-round w_in, zero reductions ----------------
__global__ void k_init(const float* __restrict__ w_in) {
    int i = blockIdx.x*256 + threadIdx.x;    // 16384 = CIN*CM
    int c = i >> 6, o = i & 63;
    g_wr[i] = tf32_big(w_in[o*CIN + c]);
    if (i < B_*CM) g_sums[i] = 0.f;
    if (i == 0) g_maxbits = 0u;
}

// ---------------- conv1x1 in: [B,256,HW] -> [B,64,HW] ----------------
__global__ __launch_bounds__(256)
void k_conv_in(const float* __restrict__ x, const float* __restrict__ b_in) {
    int bx = blockIdx.x;
    int b = bx >> 8, tile = bx & 255;
    gemm_body<CIN, false>(x + (size_t)b*CIN*HW + tile*256, g_wr, b_in,
                          g_y + (size_t)b*CM*HW + tile*256);
}

// ---------------- fused gaussian(separable) + scharr/laplacian + reductions ----------------
#define TW 64
#define TH 32
__global__ __launch_bounds__(256)
void k_edge() {
    __shared__ float ysh[TH+6][TW+8];
    __shared__ float tsh[TH+6][TW+4];
    __shared__ float smsh[TH+2][TW+4];

    const int t  = threadIdx.x;
    const int x0 = blockIdx.x*TW, y0 = blockIdx.y*TH;
    const int bc = blockIdx.z;
    const float* __restrict__ yp = g_y    + (size_t)bc*HW;
    float* __restrict__       ep = g_edge + (size_t)bc*HW;

    for (int i = t; i < (TH+6)*(TW+6); i += 256) {
        int rr = i/(TW+6), cc = i - rr*(TW+6);
        int gr = y0 - 3 + rr, gc = x0 - 3 + cc;
        float v = 0.f;
        if ((unsigned)gr < H_ && (unsigned)gc < W_) v = yp[gr*W_ + gc];
        ysh[rr][cc] = v;
    }
    __syncthreads();

    for (int i = t; i < (TH+6)*(TW+2); i += 256) {
        int rr = i/(TW+2), jj = i - rr*(TW+2);
        tsh[rr][jj] = G0*(ysh[rr][jj] + ysh[rr][jj+4])
                    + G1*(ysh[rr][jj+1] + ysh[rr][jj+3])
                    + G2* ysh[rr][jj+2];
    }
    __syncthreads();

    for (int i = t; i < (TH+2)*(TW+2); i += 256) {
        int ii = i/(TW+2), jj = i - ii*(TW+2);
        int sr = y0 - 1 + ii, sc = x0 - 1 + jj;
        float v = 0.f;
        if ((unsigned)sr < H_ && (unsigned)sc < W_)
            v = G0*(tsh[ii][jj] + tsh[ii+4][jj])
              + G1*(tsh[ii+1][jj] + tsh[ii+3][jj])
              + G2* tsh[ii+2][jj];
        smsh[ii][jj] = v;
    }
    __syncthreads();

    float lsum = 0.f, lmax = 0.f;
    for (int i = t; i < TH*TW; i += 256) {
        int ty = i >> 6, tx = i & 63;
        float a  = smsh[ty  ][tx], bb = smsh[ty  ][tx+1], c2 = smsh[ty  ][tx+2];
        float d  = smsh[ty+1][tx], e  = smsh[ty+1][tx+1], f  = smsh[ty+1][tx+2];
        float g  = smsh[ty+2][tx], h2 = smsh[ty+2][tx+1], i2 = smsh[ty+2][tx+2];
        float g0v  = 3.f*(a - c2) + 10.f*(d  - f ) + 3.f*(g  - i2);
        float g90v = 3.f*(a - g ) + 10.f*(bb - h2) + 3.f*(c2 - i2);
        float lap  = 4.f*e - bb - d - f - h2;
        float edge = fmaxf(fabsf(g0v), fabsf(g90v)) + 0.1f*fabsf(lap);
        ep[(y0+ty)*W_ + x0 + tx] = edge;
        lsum += edge;
        lmax = fmaxf(lmax, edge);
    }

#pragma unroll
    for (int off = 16; off; off >>= 1) {
        lsum += __shfl_down_sync(0xffffffffu, lsum, off);
        lmax  = fmaxf(lmax, __shfl_down_sync(0xffffffffu, lmax, off));
    }
    __shared__ float rs[8], rm[8];
    int wid = t >> 5, lane = t & 31;
    if (lane == 0) { rs[wid] = lsum; rm[wid] = lmax; }
    __syncthreads();
    if (t == 0) {
        float s = 0.f, m = 0.f;
#pragma unroll
        for (int wI = 0; wI < 8; ++wI) { s += rs[wI]; m = fmaxf(m, rm[wI]); }
        atomicAdd(&g_sums[bc], s);
        atomicMax(&g_maxbits, __float_as_uint(m));
    }
}

// ---------------- SE MLP: pooled -> scale*inv (tiny, 1 block) ----------------
__global__ void k_se(const float* __restrict__ w_fc1, const float* __restrict__ b_fc1,
                     const float* __restrict__ w_fc2, const float* __restrict__ b_fc2) {
    __shared__ float pooled[B_][CM];
    __shared__ float hsh[B_][4];
    __shared__ float inv_s;
    int t = threadIdx.x;
    if (t == 0) inv_s = 1.f/(__uint_as_float(g_maxbits) + 1e-8f);
    __syncthreads();
    float inv = inv_s;
    if (t < B_*CM)
        pooled[t>>6][t&63] = g_sums[t] * inv * (1.f/(float)HW);
    __syncthreads();
    if (t < B_*4) {
        int b = t >> 2, j = t & 3;
        float z = b_fc1[j];
        for (int c = 0; c < CM; ++c) z += w_fc1[j*CM + c]*pooled[b][c];
        hsh[b][j] = fmaxf(z, 0.f);
    }
    __syncthreads();
    if (t < B_*CM) {
        int b = t >> 6, c = t & 63;
        float z = b_fc2[c];
#pragma unroll
        for (int j = 0; j < 4; ++j) z += w_fc2[c*4 + j]*hsh[b][j];
        g_scale[t] = inv / (1.f + expf(-z));   // sigmoid * inv_max folded
    }
}

// ---------------- fold scale into tf32-rounded output weights (parallel) ----------------
__global__ void k_fold(const float* __restrict__ w_out) {
    int i = blockIdx.x*256 + threadIdx.x;    // 64 blocks -> 16384 = B*CM*CM
    int b = i >> 12, rem = i & 4095, c = rem >> 6, o = rem & 63;
    g_or[i] = tf32_big(w_out[o*CM + c] * g_scale[b*CM + c]);
}

// ---------------- conv1x1 out ----------------
__global__ __launch_bounds__(256)
void k_conv_out(const float* __restrict__ b_out, float* __restrict__ out) {
    int bx = blockIdx.x;
    int b = bx >> 8, tile = bx & 255;
    gemm_body<CM, true>(g_edge + (size_t)b*CM*HW + tile*256,
                        g_or + b*CM*CM, b_out,
                        out + (size_t)b*CM*HW + tile*256);
}

// ---------------- launch ----------------
extern "C" void kernel_launch(void* const* d_in, const int* in_sizes, int n_in,
                              void* d_out, int out_size) {
    const float* x     = (const float*)d_in[0];
    const float* w_in  = (const float*)d_in[1];
    const float* b_in  = (const float*)d_in[2];
    const float* w_fc1 = (const float*)d_in[3];
    const float* b_fc1 = (const float*)d_in[4];
    const float* w_fc2 = (const float*)d_in[5];
    const float* b_fc2 = (const float*)d_in[6];
    const float* w_out = (const float*)d_in[7];
    const float* b_out = (const float*)d_in[8];
    float* out = (float*)d_out;

    k_init<<<64, 256>>>(w_in);
    k_conv_in<<<B_*(HW/256), 256>>>(x, b_in);
    k_edge<<<dim3(W_/TW, H_/TH, B_*CM), 256>>>();
    k_se<<<1, 256>>>(w_fc1, b_fc1, w_fc2, b_fc2);
    k_fold<<<64, 256>>>(w_out);
    k_conv_out<<<B_*(HW/256), 256>>>(b_out, out);
}

// round 14
// speedup vs baseline: 1.0742x; 1.0742x over previous
#include <cuda_runtime.h>
#include <cuda_fp16.h>

#define B_  4
#define H_  256
#define W_  256
#define CIN 256
#define CM  64
#define HW  (H_*W_)

// ---------------- scratch (static device memory — no allocations) ----------------
__device__ __half g_y[(size_t)B_*CM*HW];      // 32 MB: conv_in output (fp16)
__device__ __half g_edge[(size_t)B_*CM*HW];   // 32 MB: edge_raw (fp16)
__device__ float g_wr[CIN*CM];                // w_in tf32-rounded [c][o]
__device__ float g_or[B_*CM*CM];              // folded out weights tf32-rounded [b][c][o]
__device__ float g_scale[B_*CM];              // sigmoid(..)*inv_max per (b,c)
__device__ float g_sums[B_*CM];               // per-(b,c) edge sums
__device__ unsigned int g_maxbits;            // global max (float bits, edge>=0)

// Separable gaussian taps (sigma=2, size=5)
static constexpr double GE0 = 0.6065306597126334;
static constexpr double GE1 = 0.8824969025845955;
static constexpr double GSUM = 2.0*(GE0+GE1)+1.0;
static constexpr float G0 = (float)(GE0/GSUM);
static constexpr float G1 = (float)(GE1/GSUM);
static constexpr float G2 = (float)(1.0/GSUM);

// ---------------- tf32 / async helpers ----------------
__device__ __forceinline__ float tf32_big(float x) {
    unsigned r;
    asm("cvt.rna.tf32.f32 %0, %1;" : "=r"(r) : "f"(x));
    return __uint_as_float(r);
}
__device__ __forceinline__ void mma8(float* c, const unsigned* a, unsigned b0, unsigned b1) {
    asm("mma.sync.aligned.m16n8k8.row.col.f32.tf32.tf32.f32 "
        "{%0,%1,%2,%3}, {%4,%5,%6,%7}, {%8,%9}, {%0,%1,%2,%3};"
        : "+f"(c[0]), "+f"(c[1]), "+f"(c[2]), "+f"(c[3])
        : "r"(a[0]), "r"(a[1]), "r"(a[2]), "r"(a[3]), "r"(b0), "r"(b1));
}
__device__ __forceinline__ void cp16(void* smem, const void* g) {
    unsigned s = (unsigned)__cvta_generic_to_shared(smem);
    asm volatile("cp.async.ca.shared.global [%0], [%1], 16;" :: "r"(s), "l"(g));
}
#define CP_COMMIT() asm volatile("cp.async.commit_group;" ::: "memory")
#define CP_WAIT0()  asm volatile("cp.async.wait_group 0;" ::: "memory")

// smem strides; ASTR/BSTR give conflict-free frag LDS; OSTR conflict-free STS.
#define ASTR  136   // floats  (fp32 x rows, conv_in)
#define ASTRH 264   // halves  (fp16 x rows, conv_out); 528B row pitch
#define BSTR  72
#define OSTR  132

struct alignas(16) GSmem {
    union {
        struct { float  xr[2][16*ASTR];  float wr[2][16*BSTR]; } f;  // fp32 input path
        struct { __half xr[2][16*ASTRH]; float wr[2][16*BSTR]; } h;  // fp16 input path
        float outs[64*OSTR];
    };
};

// ---------------- 1-term TF32 GEMM: [KTOT ch] x [128 px] tile -> 64 outs ----------------
// IN_HALF: x in fp16 (exact fp16->fp32->tf32, no extra rounding).
// fp32 input path feeds raw fp32 bits as tf32 (HW conversion; verified benign).
template<int KTOT, bool IN_HALF, bool OUT_HALF>
__device__ __forceinline__ void gemm_body(const void* __restrict__ xpx_,
                                          const float* __restrict__ wrp,
                                          const float* __restrict__ bias,
                                          void* __restrict__ yout_) {
    __shared__ GSmem sm;
    const int t = threadIdx.x;
    const int l = t & 31, wid = t >> 5;
    const int wm = wid & 3, wn = wid >> 2;      // 4 x 2 warp grid (px x out)
    const int lr = l >> 2, lc = l & 3;

    float acc[2][4][4];
#pragma unroll
    for (int mt = 0; mt < 2; ++mt)
#pragma unroll
        for (int nt = 0; nt < 4; ++nt)
#pragma unroll
            for (int q = 0; q < 4; ++q) acc[mt][nt][q] = 0.f;

    const int wk = t >> 4, wc = (t & 15) * 4;

    // x-load indices
    const int xk0f = t >> 5, xc0f = (t & 31) * 4;   // fp32: 2 cp16/thread
    const int xk0h = t >> 4, xc0h = (t & 15) * 8;   // fp16: 1 cp16/thread

    const float*  xf = (const float*)xpx_;
    const __half* xh = (const __half*)xpx_;

    // prologue: load chunk 0 into buf 0
    {
        if (IN_HALF) {
            cp16(&sm.h.xr[0][xk0h*ASTRH + xc0h], xh + (size_t)xk0h*HW + xc0h);
        } else {
            cp16(&sm.f.xr[0][xk0f*ASTR + xc0f],     xf + (size_t)xk0f*HW + xc0f);
            cp16(&sm.f.xr[0][(xk0f+8)*ASTR + xc0f], xf + (size_t)(xk0f+8)*HW + xc0f);
        }
        cp16(&sm.f.wr[0][wk*BSTR + wc], wrp + wk*CM + wc);
        CP_COMMIT();
    }

    int buf = 0;
    for (int kc = 0; kc < KTOT; kc += 16) {
        CP_WAIT0();
        __syncthreads();

        if (kc + 16 < KTOT) {
            int nb = buf ^ 1, kn = kc + 16;
            if (IN_HALF) {
                cp16(&sm.h.xr[nb][xk0h*ASTRH + xc0h], xh + (size_t)(kn+xk0h)*HW + xc0h);
            } else {
                cp16(&sm.f.xr[nb][xk0f*ASTR + xc0f],     xf + (size_t)(kn+xk0f)*HW + xc0f);
                cp16(&sm.f.xr[nb][(xk0f+8)*ASTR + xc0f], xf + (size_t)(kn+xk0f+8)*HW + xc0f);
            }
            cp16(&sm.f.wr[nb][wk*BSTR + wc], wrp + (kn+wk)*CM + wc);
            CP_COMMIT();
        }

        const float*  xbf = sm.f.xr[buf];
        const __half* xbh = sm.h.xr[buf];
        const float*  wb  = sm.f.wr[buf];

#pragma unroll
        for (int k8 = 0; k8 < 16; k8 += 8) {
            const int kk = k8 + lc;
            unsigned A[2][4];
#pragma unroll
            for (int mt = 0; mt < 2; ++mt) {
                const int px = wm*32 + mt*16 + lr;
                if (IN_HALF) {
                    A[mt][0] = __float_as_uint(__half2float(xbh[kk*ASTRH + px]));
                    A[mt][1] = __float_as_uint(__half2float(xbh[kk*ASTRH + px + 8]));
                    A[mt][2] = __float_as_uint(__half2float(xbh[(kk+4)*ASTRH + px]));
                    A[mt][3] = __float_as_uint(__half2float(xbh[(kk+4)*ASTRH + px + 8]));
                } else {
                    A[mt][0] = __float_as_uint(xbf[kk*ASTR + px]);
                    A[mt][1] = __float_as_uint(xbf[kk*ASTR + px + 8]);
                    A[mt][2] = __float_as_uint(xbf[(kk+4)*ASTR + px]);
                    A[mt][3] = __float_as_uint(xbf[(kk+4)*ASTR + px + 8]);
                }
            }
#pragma unroll
            for (int nt = 0; nt < 4; ++nt) {
                const int n = wn*32 + nt*8 + lr;
                unsigned B0 = __float_as_uint(wb[kk*BSTR + n]);
                unsigned B1 = __float_as_uint(wb[(kk+4)*BSTR + n]);
#pragma unroll
                for (int mt = 0; mt < 2; ++mt)
                    mma8(acc[mt][nt], A[mt], B0, B1);
            }
        }
        __syncthreads();
        buf ^= 1;
    }

    // stage C frags to smem, then coalesced store + bias
#pragma unroll
    for (int mt = 0; mt < 2; ++mt) {
#pragma unroll
        for (int nt = 0; nt < 4; ++nt) {
            int px = wm*32 + mt*16 + lr;
            int o  = wn*32 + nt*8 + 2*lc;
            sm.outs[o*OSTR + px]           = acc[mt][nt][0];
            sm.outs[(o+1)*OSTR + px]       = acc[mt][nt][1];
            sm.outs[o*OSTR + px + 8]       = acc[mt][nt][2];
            sm.outs[(o+1)*OSTR + px + 8]   = acc[mt][nt][3];
        }
    }
    __syncthreads();
#pragma unroll
    for (int p = 0; p < 8; ++p) {
        int i = p*256 + t;
        int o = i >> 5, c4 = (i & 31) * 4;
        float4 v = *(const float4*)&sm.outs[o*OSTR + c4];
        float bv = bias[o];
        v.x += bv; v.y += bv; v.z += bv; v.w += bv;
        if (OUT_HALF) {
            __half2 h0 = __floats2half2_rn(v.x, v.y);
            __half2 h1 = __floats2half2_rn(v.z, v.w);
            uint2 pk;
            pk.x = *reinterpret_cast<unsigned*>(&h0);
            pk.y = *reinterpret_cast<unsigned*>(&h1);
            *reinterpret_cast<uint2*>((__half*)yout_ + (size_t)o*HW + c4) = pk;
        } else {
            *(float4*)((float*)yout_ + (size_t)o*HW + c4) = v;
        }
    }
}

// ---------------- init: tf32-round w_in, zero reductions ----------------
__global__ void k_init(const float* __restrict__ w_in) {
    int i = blockIdx.x*256 + threadIdx.x;    // 16384 = CIN*CM
    int c = i >> 6, o = i & 63;
    g_wr[i] = tf32_big(w_in[o*CIN + c]);
    if (i < B_*CM) g_sums[i] = 0.f;
    if (i == 0) g_maxbits = 0u;
}

// ---------------- conv1x1 in: [B,256,HW] fp32 -> [B,64,HW] fp16 ----------------
__global__ __launch_bounds__(256)
void k_conv_in(const float* __restrict__ x, const float* __restrict__ b_in) {
    int bx = blockIdx.x;
    int b = bx >> 9, tile = bx & 511;
    gemm_body<CIN, false, true>(x + (size_t)b*CIN*HW + tile*128, g_wr, b_in,
                                g_y + (size_t)b*CM*HW + tile*128);
}

// ---------------- fused gaussian(separable) + scharr/laplacian + reductions ----------------
#define TW 64
#define TH 32
__global__ __launch_bounds__(256)
void k_edge() {
    __shared__ float ysh[TH+6][TW+8];
    __shared__ float tsh[TH+6][TW+4];
    __shared__ float smsh[TH+2][TW+4];

    const int t  = threadIdx.x;
    const int x0 = blockIdx.x*TW, y0 = blockIdx.y*TH;
    const int bc = blockIdx.z;
    const __half* __restrict__ yp = g_y    + (size_t)bc*HW;
    __half* __restrict__       ep = g_edge + (size_t)bc*HW;

    for (int i = t; i < (TH+6)*(TW+6); i += 256) {
        int rr = i/(TW+6), cc = i - rr*(TW+6);
        int gr = y0 - 3 + rr, gc = x0 - 3 + cc;
        float v = 0.f;
        if ((unsigned)gr < H_ && (unsigned)gc < W_) v = __half2float(yp[gr*W_ + gc]);
        ysh[rr][cc] = v;
    }
    __syncthreads();

    for (int i = t; i < (TH+6)*(TW+2); i += 256) {
        int rr = i/(TW+2), jj = i - rr*(TW+2);
        tsh[rr][jj] = G0*(ysh[rr][jj] + ysh[rr][jj+4])
                    + G1*(ysh[rr][jj+1] + ysh[rr][jj+3])
                    + G2* ysh[rr][jj+2];
    }
    __syncthreads();

    for (int i = t; i < (TH+2)*(TW+2); i += 256) {
        int ii = i/(TW+2), jj = i - ii*(TW+2);
        int sr = y0 - 1 + ii, sc = x0 - 1 + jj;
        float v = 0.f;
        if ((unsigned)sr < H_ && (unsigned)sc < W_)
            v = G0*(tsh[ii][jj] + tsh[ii+4][jj])
              + G1*(tsh[ii+1][jj] + tsh[ii+3][jj])
              + G2* tsh[ii+2][jj];
        smsh[ii][jj] = v;
    }
    __syncthreads();

    float lsum = 0.f, lmax = 0.f;
    for (int i = t; i < TH*TW; i += 256) {
        int ty = i >> 6, tx = i & 63;
        float a  = smsh[ty  ][tx], bb = smsh[ty  ][tx+1], c2 = smsh[ty  ][tx+2];
        float d  = smsh[ty+1][tx], e  = smsh[ty+1][tx+1], f  = smsh[ty+1][tx+2];
        float g  = smsh[ty+2][tx], h2 = smsh[ty+2][tx+1], i2 = smsh[ty+2][tx+2];
        float g0v  = 3.f*(a - c2) + 10.f*(d  - f ) + 3.f*(g  - i2);
        float g90v = 3.f*(a - g ) + 10.f*(bb - h2) + 3.f*(c2 - i2);
        float lap  = 4.f*e - bb - d - f - h2;
        float edge = fmaxf(fabsf(g0v), fabsf(g90v)) + 0.1f*fabsf(lap);
        ep[(y0+ty)*W_ + x0 + tx] = __float2half(edge);
        lsum += edge;
        lmax = fmaxf(lmax, edge);
    }

#pragma unroll
    for (int off = 16; off; off >>= 1) {
        lsum += __shfl_down_sync(0xffffffffu, lsum, off);
        lmax  = fmaxf(lmax, __shfl_down_sync(0xffffffffu, lmax, off));
    }
    __shared__ float rs[8], rm[8];
    int wid = t >> 5, lane = t & 31;
    if (lane == 0) { rs[wid] = lsum; rm[wid] = lmax; }
    __syncthreads();
    if (t == 0) {
        float s = 0.f, m = 0.f;
#pragma unroll
        for (int wI = 0; wI < 8; ++wI) { s += rs[wI]; m = fmaxf(m, rm[wI]); }
        atomicAdd(&g_sums[bc], s);
        atomicMax(&g_maxbits, __float_as_uint(m));
    }
}

// ---------------- SE MLP: pooled -> scale*inv (tiny, 1 block) ----------------
__global__ void k_se(const float* __restrict__ w_fc1, const float* __restrict__ b_fc1,
                     const float* __restrict__ w_fc2, const float* __restrict__ b_fc2) {
    __shared__ float pooled[B_][CM];
    __shared__ float hsh[B_][4];
    __shared__ float inv_s;
    int t = threadIdx.x;
    if (t == 0) inv_s = 1.f/(__uint_as_float(g_maxbits) + 1e-8f);
    __syncthreads();
    float inv = inv_s;
    if (t < B_*CM)
        pooled[t>>6][t&63] = g_sums[t] * inv * (1.f/(float)HW);
    __syncthreads();
    if (t < B_*4) {
        int b = t >> 2, j = t & 3;
        float z = b_fc1[j];
        for (int c = 0; c < CM; ++c) z += w_fc1[j*CM + c]*pooled[b][c];
        hsh[b][j] = fmaxf(z, 0.f);
    }
    __syncthreads();
    if (t < B_*CM) {
        int b = t >> 6, c = t & 63;
        float z = b_fc2[c];
#pragma unroll
        for (int j = 0; j < 4; ++j) z += w_fc2[c*4 + j]*hsh[b][j];
        g_scale[t] = inv / (1.f + expf(-z));   // sigmoid * inv_max folded
    }
}

// ---------------- fold scale into tf32-rounded output weights (parallel) ----------------
__global__ void k_fold(const float* __restrict__ w_out) {
    int i = blockIdx.x*256 + threadIdx.x;    // 64 blocks -> 16384 = B*CM*CM
    int b = i >> 12, rem = i & 4095, c = rem >> 6, o = rem & 63;
    g_or[i] = tf32_big(w_out[o*CM + c] * g_scale[b*CM + c]);
}

// ---------------- conv1x1 out: [B,64,HW] fp16 -> [B,64,HW] fp32 ----------------
__global__ __launch_bounds__(256)
void k_conv_out(const float* __restrict__ b_out, float* __restrict__ out) {
    int bx = blockIdx.x;
    int b = bx >> 9, tile = bx & 511;
    gemm_body<CM, true, false>(g_edge + (size_t)b*CM*HW + tile*128,
                               g_or + b*CM*CM, b_out,
                               out + (size_t)b*CM*HW + tile*128);
}

// ---------------- launch ----------------
extern "C" void kernel_launch(void* const* d_in, const int* in_sizes, int n_in,
                              void* d_out, int out_size) {
    const float* x     = (const float*)d_in[0];
    const float* w_in  = (const float*)d_in[1];
    const float* b_in  = (const float*)d_in[2];
    const float* w_fc1 = (const float*)d_in[3];
    const float* b_fc1 = (const float*)d_in[4];
    const float* w_fc2 = (const float*)d_in[5];
    const float* b_fc2 = (const float*)d_in[6];
    const float* w_out = (const float*)d_in[7];
    const float* b_out = (const float*)d_in[8];
    float* out = (float*)d_out;

    k_init<<<64, 256>>>(w_in);
    k_conv_in<<<B_*(HW/128), 256>>>(x, b_in);
    k_edge<<<dim3(W_/TW, H_/TH, B_*CM), 256>>>();
    k_se<<<1, 256>>>(w_fc1, b_fc1, w_fc2, b_fc2);
    k_fold<<<64, 256>>>(w_out);
    k_conv_out<<<B_*(HW/128), 256>>>(b_out, out);
}

// round 15
// speedup vs baseline: 1.0769x; 1.0025x over previous
#include <cuda_runtime.h>
#include <cuda_fp16.h>

#define B_  4
#define H_  256
#define W_  256
#define CIN 256
#define CM  64
#define HW  (H_*W_)

// ---------------- scratch (static device memory — no allocations) ----------------
__device__ __half g_y[(size_t)B_*CM*HW];      // 32 MB: conv_in output (fp16)
__device__ __half g_edge[(size_t)B_*CM*HW];   // 32 MB: edge_raw (fp16)
__device__ __half2 g_wh[(CIN/2)*CM];          // w_in fp16 pairs [k2][o] = (w[2k2][o], w[2k2+1][o])
__device__ __half2 g_oh[B_*(CM/2)*CM];        // folded out weights fp16 pairs [b][k2][o]
__device__ float g_scale[B_*CM];              // sigmoid(..)*inv_max per (b,c)
__device__ float g_sums[B_*CM];               // per-(b,c) edge sums
__device__ unsigned int g_maxbits;            // global max (float bits, edge>=0)

// Separable gaussian taps (sigma=2, size=5)
static constexpr double GE0 = 0.6065306597126334;
static constexpr double GE1 = 0.8824969025845955;
static constexpr double GSUM = 2.0*(GE0+GE1)+1.0;
static constexpr float G0 = (float)(GE0/GSUM);
static constexpr float G1 = (float)(GE1/GSUM);
static constexpr float G2 = (float)(1.0/GSUM);

// ---------------- mma / async helpers ----------------
__device__ __forceinline__ void mma16(float* c, const unsigned* a, unsigned b0, unsigned b1) {
    asm("mma.sync.aligned.m16n8k16.row.col.f32.f16.f16.f32 "
        "{%0,%1,%2,%3}, {%4,%5,%6,%7}, {%8,%9}, {%0,%1,%2,%3};"
        : "+f"(c[0]), "+f"(c[1]), "+f"(c[2]), "+f"(c[3])
        : "r"(a[0]), "r"(a[1]), "r"(a[2]), "r"(a[3]), "r"(b0), "r"(b1));
}
__device__ __forceinline__ void ldmatrix4t(unsigned* r, const void* smem) {
    unsigned s = (unsigned)__cvta_generic_to_shared(smem);
    asm volatile("ldmatrix.sync.aligned.m8n8.x4.trans.shared.b16 {%0,%1,%2,%3}, [%4];"
        : "=r"(r[0]), "=r"(r[1]), "=r"(r[2]), "=r"(r[3]) : "r"(s));
}
__device__ __forceinline__ unsigned packh2(float lo, float hi) {
    __half2 h = __floats2half2_rn(lo, hi);
    return *reinterpret_cast<unsigned*>(&h);
}
__device__ __forceinline__ void cp16(void* smem, const void* g) {
    unsigned s = (unsigned)__cvta_generic_to_shared(smem);
    asm volatile("cp.async.ca.shared.global [%0], [%1], 16;" :: "r"(s), "l"(g));
}
#define CP_COMMIT() asm volatile("cp.async.commit_group;" ::: "memory")
#define CP_WAIT0()  asm volatile("cp.async.wait_group 0;" ::: "memory")

// smem strides, conflict-free for the fp16 frag patterns:
#define ASTR  132   // fp32 x rows (conv_in): 2*132 % 32 == 8
#define ASTRH 264   // fp16 x rows (conv_out), halves: 132 words % 32 == 4 (ldmatrix)
#define B2STR 72    // half2 w rows: 72 % 32 == 8
#define OSTR  132

struct alignas(16) GSmem {
    union {
        struct { float  xr[2][16*ASTR];  __half2 wh[2][8*B2STR]; } f;  // conv_in
        struct { __half xr[2][16*ASTRH]; __half2 wh[2][8*B2STR]; } h;  // conv_out
        float outs[64*OSTR];
    };
};

// ---------------- fp16 MMA GEMM: [KTOT ch] x [128 px] tile -> 64 outs ----------------
template<int KTOT, bool IN_HALF, bool OUT_HALF>
__device__ __forceinline__ void gemm_body(const void* __restrict__ xpx_,
                                          const __half2* __restrict__ whp,  // paired [k2][o]
                                          const float* __restrict__ bias,
                                          void* __restrict__ yout_) {
    __shared__ GSmem sm;
    const int t = threadIdx.x;
    const int l = t & 31, wid = t >> 5;
    const int wm = wid & 3, wn = wid >> 2;      // 4 x 2 warp grid (px x out)
    const int lr = l >> 2, lc = l & 3;

    float acc[2][4][4];
#pragma unroll
    for (int mt = 0; mt < 2; ++mt)
#pragma unroll
        for (int nt = 0; nt < 4; ++nt)
#pragma unroll
            for (int q = 0; q < 4; ++q) acc[mt][nt][q] = 0.f;

    // w load: 8 rows x 64 half2 per chunk = 128 cp16 (threads 0..127)
    const int wk2 = t >> 4, woc = (t & 15) * 4;
    // x load indices
    const int xk0f = t >> 5, xc0f = (t & 31) * 4;   // fp32: 2 cp16/thread
    const int xk0h = t >> 4, xc0h = (t & 15) * 8;   // fp16: 1 cp16/thread

    const float*  xf = (const float*)xpx_;
    const __half* xh = (const __half*)xpx_;

    // prologue
    {
        if (IN_HALF) {
            cp16(&sm.h.xr[0][xk0h*ASTRH + xc0h], xh + (size_t)xk0h*HW + xc0h);
        } else {
            cp16(&sm.f.xr[0][xk0f*ASTR + xc0f],     xf + (size_t)xk0f*HW + xc0f);
            cp16(&sm.f.xr[0][(xk0f+8)*ASTR + xc0f], xf + (size_t)(xk0f+8)*HW + xc0f);
        }
        if (t < 128) cp16(&sm.f.wh[0][wk2*B2STR + woc], whp + wk2*CM + woc);
        CP_COMMIT();
    }

    int buf = 0;
    for (int kc = 0; kc < KTOT; kc += 16) {
        CP_WAIT0();
        __syncthreads();

        if (kc + 16 < KTOT) {
            int nb = buf ^ 1, kn = kc + 16;
            if (IN_HALF) {
                cp16(&sm.h.xr[nb][xk0h*ASTRH + xc0h], xh + (size_t)(kn+xk0h)*HW + xc0h);
            } else {
                cp16(&sm.f.xr[nb][xk0f*ASTR + xc0f],     xf + (size_t)(kn+xk0f)*HW + xc0f);
                cp16(&sm.f.xr[nb][(xk0f+8)*ASTR + xc0f], xf + (size_t)(kn+xk0f+8)*HW + xc0f);
            }
            if (t < 128) cp16(&sm.f.wh[nb][wk2*B2STR + woc], whp + (kn/2 + wk2)*CM + woc);
            CP_COMMIT();
        }

        const float*   xbf = sm.f.xr[buf];
        const __half*  xbh = sm.h.xr[buf];
        const __half2* wb  = sm.f.wh[buf];

        // one m16n8k16 step covers the whole 16-ch chunk
        unsigned A[2][4];
#pragma unroll
        for (int mt = 0; mt < 2; ++mt) {
            const int pxb = wm*32 + mt*16;
            if (IN_HALF) {
                // ldmatrix.x4.trans from [k][px] halves
                const int krow = (l & 7) + ((l & 16) ? 8 : 0);
                const int col  = pxb + ((l & 8) ? 8 : 0);
                ldmatrix4t(A[mt], &xbh[krow*ASTRH + col]);
            } else {
                const int px = pxb + lr;
                A[mt][0] = packh2(xbf[(2*lc)*ASTR + px],       xbf[(2*lc+1)*ASTR + px]);
                A[mt][1] = packh2(xbf[(2*lc)*ASTR + px + 8],   xbf[(2*lc+1)*ASTR + px + 8]);
                A[mt][2] = packh2(xbf[(8+2*lc)*ASTR + px],     xbf[(9+2*lc)*ASTR + px]);
                A[mt][3] = packh2(xbf[(8+2*lc)*ASTR + px + 8], xbf[(9+2*lc)*ASTR + px + 8]);
            }
        }
#pragma unroll
        for (int nt = 0; nt < 4; ++nt) {
            const int n = wn*32 + nt*8 + lr;
            unsigned B0 = *reinterpret_cast<const unsigned*>(&wb[lc*B2STR + n]);
            unsigned B1 = *reinterpret_cast<const unsigned*>(&wb[(4+lc)*B2STR + n]);
#pragma unroll
            for (int mt = 0; mt < 2; ++mt)
                mma16(acc[mt][nt], A[mt], B0, B1);
        }
        __syncthreads();
        buf ^= 1;
    }

    // stage C frags to smem, then coalesced store + bias (same C layout as tf32 path)
#pragma unroll
    for (int mt = 0; mt < 2; ++mt) {
#pragma unroll
        for (int nt = 0; nt < 4; ++nt) {
            int px = wm*32 + mt*16 + lr;
            int o  = wn*32 + nt*8 + 2*lc;
            sm.outs[o*OSTR + px]           = acc[mt][nt][0];
            sm.outs[(o+1)*OSTR + px]       = acc[mt][nt][1];
            sm.outs[o*OSTR + px + 8]       = acc[mt][nt][2];
            sm.outs[(o+1)*OSTR + px + 8]   = acc[mt][nt][3];
        }
    }
    __syncthreads();
#pragma unroll
    for (int p = 0; p < 8; ++p) {
        int i = p*256 + t;
        int o = i >> 5, c4 = (i & 31) * 4;
        float4 v = *(const float4*)&sm.outs[o*OSTR + c4];
        float bv = bias[o];
        v.x += bv; v.y += bv; v.z += bv; v.w += bv;
        if (OUT_HALF) {
            __half2 h0 = __floats2half2_rn(v.x, v.y);
            __half2 h1 = __floats2half2_rn(v.z, v.w);
            uint2 pk;
            pk.x = *reinterpret_cast<unsigned*>(&h0);
            pk.y = *reinterpret_cast<unsigned*>(&h1);
            *reinterpret_cast<uint2*>((__half*)yout_ + (size_t)o*HW + c4) = pk;
        } else {
            *(float4*)((float*)yout_ + (size_t)o*HW + c4) = v;
        }
    }
}

// ---------------- init: pair w_in into fp16, zero reductions ----------------
__global__ void k_init(const float* __restrict__ w_in) {
    int i = blockIdx.x*256 + threadIdx.x;    // 16384 threads; 8192 = (CIN/2)*CM pairs
    if (i < (CIN/2)*CM) {
        int k2 = i >> 6, o = i & 63;
        g_wh[i] = __floats2half2_rn(w_in[o*CIN + 2*k2], w_in[o*CIN + 2*k2 + 1]);
    }
    if (i < B_*CM) g_sums[i] = 0.f;
    if (i == 0) g_maxbits = 0u;
}

// ---------------- conv1x1 in: [B,256,HW] fp32 -> [B,64,HW] fp16 ----------------
__global__ __launch_bounds__(256)
void k_conv_in(const float* __restrict__ x, const float* __restrict__ b_in) {
    int bx = blockIdx.x;
    int b = bx >> 9, tile = bx & 511;
    gemm_body<CIN, false, true>(x + (size_t)b*CIN*HW + tile*128, g_wh, b_in,
                                g_y + (size_t)b*CM*HW + tile*128);
}

// ---------------- fused gaussian(separable) + scharr/laplacian + reductions ----------------
#define TW 64
#define TH 32
__global__ __launch_bounds__(256)
void k_edge() {
    __shared__ float ysh[TH+6][TW+8];
    __shared__ float tsh[TH+6][TW+4];
    __shared__ float smsh[TH+2][TW+4];

    const int t  = threadIdx.x;
    const int x0 = blockIdx.x*TW, y0 = blockIdx.y*TH;
    const int bc = blockIdx.z;
    const __half* __restrict__ yp = g_y    + (size_t)bc*HW;
    __half* __restrict__       ep = g_edge + (size_t)bc*HW;

    for (int i = t; i < (TH+6)*(TW+6); i += 256) {
        int rr = i/(TW+6), cc = i - rr*(TW+6);
        int gr = y0 - 3 + rr, gc = x0 - 3 + cc;
        float v = 0.f;
        if ((unsigned)gr < H_ && (unsigned)gc < W_) v = __half2float(yp[gr*W_ + gc]);
        ysh[rr][cc] = v;
    }
    __syncthreads();

    for (int i = t; i < (TH+6)*(TW+2); i += 256) {
        int rr = i/(TW+2), jj = i - rr*(TW+2);
        tsh[rr][jj] = G0*(ysh[rr][jj] + ysh[rr][jj+4])
                    + G1*(ysh[rr][jj+1] + ysh[rr][jj+3])
                    + G2* ysh[rr][jj+2];
    }
    __syncthreads();

    for (int i = t; i < (TH+2)*(TW+2); i += 256) {
        int ii = i/(TW+2), jj = i - ii*(TW+2);
        int sr = y0 - 1 + ii, sc = x0 - 1 + jj;
        float v = 0.f;
        if ((unsigned)sr < H_ && (unsigned)sc < W_)
            v = G0*(tsh[ii][jj] + tsh[ii+4][jj])
              + G1*(tsh[ii+1][jj] + tsh[ii+3][jj])
              + G2* tsh[ii+2][jj];
        smsh[ii][jj] = v;
    }
    __syncthreads();

    float lsum = 0.f, lmax = 0.f;
    for (int i = t; i < TH*TW; i += 256) {
        int ty = i >> 6, tx = i & 63;
        float a  = smsh[ty  ][tx], bb = smsh[ty  ][tx+1], c2 = smsh[ty  ][tx+2];
        float d  = smsh[ty+1][tx], e  = smsh[ty+1][tx+1], f  = smsh[ty+1][tx+2];
        float g  = smsh[ty+2][tx], h2 = smsh[ty+2][tx+1], i2 = smsh[ty+2][tx+2];
        float g0v  = 3.f*(a - c2) + 10.f*(d  - f ) + 3.f*(g  - i2);
        float g90v = 3.f*(a - g ) + 10.f*(bb - h2) + 3.f*(c2 - i2);
        float lap  = 4.f*e - bb - d - f - h2;
        float edge = fmaxf(fabsf(g0v), fabsf(g90v)) + 0.1f*fabsf(lap);
        ep[(y0+ty)*W_ + x0 + tx] = __float2half(edge);
        lsum += edge;
        lmax = fmaxf(lmax, edge);
    }

#pragma unroll
    for (int off = 16; off; off >>= 1) {
        lsum += __shfl_down_sync(0xffffffffu, lsum, off);
        lmax  = fmaxf(lmax, __shfl_down_sync(0xffffffffu, lmax, off));
    }
    __shared__ float rs[8], rm[8];
    int wid = t >> 5, lane = t & 31;
    if (lane == 0) { rs[wid] = lsum; rm[wid] = lmax; }
    __syncthreads();
    if (t == 0) {
        float s = 0.f, m = 0.f;
#pragma unroll
        for (int wI = 0; wI < 8; ++wI) { s += rs[wI]; m = fmaxf(m, rm[wI]); }
        atomicAdd(&g_sums[bc], s);
        atomicMax(&g_maxbits, __float_as_uint(m));
    }
}

// ---------------- SE MLP: pooled -> scale*inv (tiny, 1 block) ----------------
__global__ void k_se(const float* __restrict__ w_fc1, const float* __restrict__ b_fc1,
                     const float* __restrict__ w_fc2, const float* __restrict__ b_fc2) {
    __shared__ float pooled[B_][CM];
    __shared__ float hsh[B_][4];
    __shared__ float inv_s;
    int t = threadIdx.x;
    if (t == 0) inv_s = 1.f/(__uint_as_float(g_maxbits) + 1e-8f);
    __syncthreads();
    float inv = inv_s;
    if (t < B_*CM)
        pooled[t>>6][t&63] = g_sums[t] * inv * (1.f/(float)HW);
    __syncthreads();
    if (t < B_*4) {
        int b = t >> 2, j = t & 3;
        float z = b_fc1[j];
        for (int c = 0; c < CM; ++c) z += w_fc1[j*CM + c]*pooled[b][c];
        hsh[b][j] = fmaxf(z, 0.f);
    }
    __syncthreads();
    if (t < B_*CM) {
        int b = t >> 6, c = t & 63;
        float z = b_fc2[c];
#pragma unroll
        for (int j = 0; j < 4; ++j) z += w_fc2[c*4 + j]*hsh[b][j];
        g_scale[t] = inv / (1.f + expf(-z));   // sigmoid * inv_max folded
    }
}

// ---------------- fold scale into fp16-paired output weights (parallel) ----------------
__global__ void k_fold(const float* __restrict__ w_out) {
    int i = blockIdx.x*256 + threadIdx.x;    // 32 blocks -> 8192 = B*(CM/2)*CM
    int o = i & 63, k2 = (i >> 6) & 31, b = i >> 11;
    float v0 = w_out[o*CM + 2*k2]     * g_scale[b*CM + 2*k2];
    float v1 = w_out[o*CM + 2*k2 + 1] * g_scale[b*CM + 2*k2 + 1];
    g_oh[i] = __floats2half2_rn(v0, v1);
}

// ---------------- conv1x1 out: [B,64,HW] fp16 -> [B,64,HW] fp32 ----------------
__global__ __launch_bounds__(256)
void k_conv_out(const float* __restrict__ b_out, float* __restrict__ out) {
    int bx = blockIdx.x;
    int b = bx >> 9, tile = bx & 511;
    gemm_body<CM, true, false>(g_edge + (size_t)b*CM*HW + tile*128,
                               g_oh + b*(CM/2)*CM, b_out,
                               out + (size_t)b*CM*HW + tile*128);
}

// ---------------- launch ----------------
extern "C" void kernel_launch(void* const* d_in, const int* in_sizes, int n_in,
                              void* d_out, int out_size) {
    const float* x     = (const float*)d_in[0];
    const float* w_in  = (const float*)d_in[1];
    const float* b_in  = (const float*)d_in[2];
    const float* w_fc1 = (const float*)d_in[3];
    const float* b_fc1 = (const float*)d_in[4];
    const float* w_fc2 = (const float*)d_in[5];
    const float* b_fc2 = (const float*)d_in[6];
    const float* w_out = (const float*)d_in[7];
    const float* b_out = (const float*)d_in[8];
    float* out = (float*)d_out;

    k_init<<<64, 256>>>(w_in);
    k_conv_in<<<B_*(HW/128), 256>>>(x, b_in);
    k_edge<<<dim3(W_/TW, H_/TH, B_*CM), 256>>>();
    k_se<<<1, 256>>>(w_fc1, b_fc1, w_fc2, b_fc2);
    k_fold<<<32, 256>>>(w_out);
    k_conv_out<<<B_*(HW/128), 256>>>(b_out, out);
}

// round 17
// speedup vs baseline: 1.2046x; 1.1187x over previous
#include <cuda_runtime.h>
#include <cuda_fp16.h>

#define B_  4
#define H_  256
#define W_  256
#define CIN 256
#define CM  64
#define HW  (H_*W_)

// ---------------- scratch (static device memory — no allocations) ----------------
__device__ __half g_y[(size_t)B_*CM*HW];      // 32 MB: conv_in output (fp16)
__device__ __half g_edge[(size_t)B_*CM*HW];   // 32 MB: edge_raw (fp16)
__device__ __half2 g_wh[(CIN/2)*CM];          // w_in fp16 pairs [k2][o]
__device__ __half2 g_oh[B_*(CM/2)*CM];        // folded out weights fp16 pairs [b][k2][o]
__device__ float g_scale[B_*CM];              // sigmoid(..)*inv_max per (b,c)
__device__ float g_sums[B_*CM];               // per-(b,c) edge sums
__device__ unsigned int g_maxbits;            // global max (float bits, edge>=0)

// Separable gaussian taps (sigma=2, size=5)
static constexpr double GE0 = 0.6065306597126334;
static constexpr double GE1 = 0.8824969025845955;
static constexpr double GSUM = 2.0*(GE0+GE1)+1.0;
static constexpr float G0 = (float)(GE0/GSUM);
static constexpr float G1 = (float)(GE1/GSUM);
static constexpr float G2 = (float)(1.0/GSUM);

// ---------------- mma / async helpers ----------------
__device__ __forceinline__ void mma16(float* c, const unsigned* a, unsigned b0, unsigned b1) {
    asm("mma.sync.aligned.m16n8k16.row.col.f32.f16.f16.f32 "
        "{%0,%1,%2,%3}, {%4,%5,%6,%7}, {%8,%9}, {%0,%1,%2,%3};"
        : "+f"(c[0]), "+f"(c[1]), "+f"(c[2]), "+f"(c[3])
        : "r"(a[0]), "r"(a[1]), "r"(a[2]), "r"(a[3]), "r"(b0), "r"(b1));
}
__device__ __forceinline__ void ldmatrix4t(unsigned* r, const void* smem) {
    unsigned s = (unsigned)__cvta_generic_to_shared(smem);
    asm volatile("ldmatrix.sync.aligned.m8n8.x4.trans.shared.b16 {%0,%1,%2,%3}, [%4];"
        : "=r"(r[0]), "=r"(r[1]), "=r"(r[2]), "=r"(r[3]) : "r"(s));
}
__device__ __forceinline__ unsigned packh2(float lo, float hi) {
    __half2 h = __floats2half2_rn(lo, hi);
    return *reinterpret_cast<unsigned*>(&h);
}
__device__ __forceinline__ void cp16(void* smem, const void* g) {
    unsigned s = (unsigned)__cvta_generic_to_shared(smem);
    asm volatile("cp.async.ca.shared.global [%0], [%1], 16;" :: "r"(s), "l"(g));
}
#define CP_COMMIT() asm volatile("cp.async.commit_group;" ::: "memory")
#define CP_WAIT2()  asm volatile("cp.async.wait_group 2;" ::: "memory")

#define NSTAGE 4

// smem strides, conflict-free for the fp16 frag patterns:
#define ASTR  132   // fp32 x rows (conv_in)
#define ASTRH 264   // fp16 x rows (conv_out), halves
#define B2STR 72    // half2 w rows
#define OSTR  132

struct alignas(16) GSmem {
    union {
        struct { float  xr[NSTAGE][16*ASTR];  __half2 wh[NSTAGE][8*B2STR]; } f;  // conv_in
        struct { __half xr[NSTAGE][16*ASTRH]; __half2 wh[NSTAGE][8*B2STR]; } h;  // conv_out
        float outs[64*OSTR];
    };
};

// ---------------- fp16 MMA GEMM: [KTOT ch] x [128 px] tile -> 64 outs, 4-stage pipeline ----------------
// Invariant: EVERY loop iteration commits exactly one cp.async group (empty at the
// tail), so wait_group 2 at the top of iteration ch always implies chunk ch landed.
template<int KTOT, bool IN_HALF, bool OUT_HALF>
__device__ __forceinline__ void gemm_body(const void* __restrict__ xpx_,
                                          const __half2* __restrict__ whp,
                                          const float* __restrict__ bias,
                                          void* __restrict__ yout_) {
    __shared__ GSmem sm;
    const int t = threadIdx.x;
    const int l = t & 31, wid = t >> 5;
    const int wm = wid & 3, wn = wid >> 2;      // 4 x 2 warp grid (px x out)
    const int lr = l >> 2, lc = l & 3;
    constexpr int NCH = KTOT / 16;

    float acc[2][4][4];
#pragma unroll
    for (int mt = 0; mt < 2; ++mt)
#pragma unroll
        for (int nt = 0; nt < 4; ++nt)
#pragma unroll
            for (int q = 0; q < 4; ++q) acc[mt][nt][q] = 0.f;

    const int wk2 = t >> 4, woc = (t & 15) * 4;
    const int xk0f = t >> 5, xc0f = (t & 31) * 4;   // fp32: 2 cp16/thread
    const int xk0h = t >> 4, xc0h = (t & 15) * 8;   // fp16: 1 cp16/thread

    const float*  xf = (const float*)xpx_;
    const __half* xh = (const __half*)xpx_;

    // issue loads for one chunk into stage s (NO commit here)
    auto load_chunk = [&](int chunk, int s) {
        int kn = chunk * 16;
        if (IN_HALF) {
            cp16(&sm.h.xr[s][xk0h*ASTRH + xc0h], xh + (size_t)(kn+xk0h)*HW + xc0h);
        } else {
            cp16(&sm.f.xr[s][xk0f*ASTR + xc0f],     xf + (size_t)(kn+xk0f)*HW + xc0f);
            cp16(&sm.f.xr[s][(xk0f+8)*ASTR + xc0f], xf + (size_t)(kn+xk0f+8)*HW + xc0f);
        }
        if (t < 128) cp16(&sm.f.wh[s][wk2*B2STR + woc], whp + (kn/2 + wk2)*CM + woc);
    };

    // prologue: fill 3 stages, one commit each (groups 0,1,2 = chunks 0,1,2)
#pragma unroll
    for (int c = 0; c < 3; ++c) {
        if (c < NCH) load_chunk(c, c);
        CP_COMMIT();
    }

    for (int ch = 0; ch < NCH; ++ch) {
        CP_WAIT2();             // groups 0..ch complete -> chunk ch resident
        __syncthreads();        // all reads of stage (ch+3)&3 from iter ch-1 done

        if (ch + 3 < NCH) load_chunk(ch + 3, (ch + 3) & (NSTAGE-1));
        CP_COMMIT();            // unconditional: keeps group count == iteration count

        const int buf = ch & (NSTAGE-1);
        const float*   xbf = sm.f.xr[buf];
        const __half*  xbh = sm.h.xr[buf];
        const __half2* wb  = sm.f.wh[buf];

        unsigned A[2][4];
#pragma unroll
        for (int mt = 0; mt < 2; ++mt) {
            const int pxb = wm*32 + mt*16;
            if (IN_HALF) {
                const int krow = (l & 7) + ((l & 16) ? 8 : 0);
                const int col  = pxb + ((l & 8) ? 8 : 0);
                ldmatrix4t(A[mt], &xbh[krow*ASTRH + col]);
            } else {
                const int px = pxb + lr;
                A[mt][0] = packh2(xbf[(2*lc)*ASTR + px],       xbf[(2*lc+1)*ASTR + px]);
                A[mt][1] = packh2(xbf[(2*lc)*ASTR + px + 8],   xbf[(2*lc+1)*ASTR + px + 8]);
                A[mt][2] = packh2(xbf[(8+2*lc)*ASTR + px],     xbf[(9+2*lc)*ASTR + px]);
                A[mt][3] = packh2(xbf[(8+2*lc)*ASTR + px + 8], xbf[(9+2*lc)*ASTR + px + 8]);
            }
        }
#pragma unroll
        for (int nt = 0; nt < 4; ++nt) {
            const int n = wn*32 + nt*8 + lr;
            unsigned B0 = *reinterpret_cast<const unsigned*>(&wb[lc*B2STR + n]);
            unsigned B1 = *reinterpret_cast<const unsigned*>(&wb[(4+lc)*B2STR + n]);
#pragma unroll
            for (int mt = 0; mt < 2; ++mt)
                mma16(acc[mt][nt], A[mt], B0, B1);
        }
    }
    __syncthreads();

    // stage C frags to smem, then coalesced store + bias
#pragma unroll
    for (int mt = 0; mt < 2; ++mt) {
#pragma unroll
        for (int nt = 0; nt < 4; ++nt) {
            int px = wm*32 + mt*16 + lr;
            int o  = wn*32 + nt*8 + 2*lc;
            sm.outs[o*OSTR + px]           = acc[mt][nt][0];
            sm.outs[(o+1)*OSTR + px]       = acc[mt][nt][1];
            sm.outs[o*OSTR + px + 8]       = acc[mt][nt][2];
            sm.outs[(o+1)*OSTR + px + 8]   = acc[mt][nt][3];
        }
    }
    __syncthreads();
#pragma unroll
    for (int p = 0; p < 8; ++p) {
        int i = p*256 + t;
        int o = i >> 5, c4 = (i & 31) * 4;
        float4 v = *(const float4*)&sm.outs[o*OSTR + c4];
        float bv = bias[o];
        v.x += bv; v.y += bv; v.z += bv; v.w += bv;
        if (OUT_HALF) {
            __half2 h0 = __floats2half2_rn(v.x, v.y);
            __half2 h1 = __floats2half2_rn(v.z, v.w);
            uint2 pk;
            pk.x = *reinterpret_cast<unsigned*>(&h0);
            pk.y = *reinterpret_cast<unsigned*>(&h1);
            *reinterpret_cast<uint2*>((__half*)yout_ + (size_t)o*HW + c4) = pk;
        } else {
            *(float4*)((float*)yout_ + (size_t)o*HW + c4) = v;
        }
    }
}

// ---------------- init: pair w_in into fp16, zero reductions ----------------
__global__ void k_init(const float* __restrict__ w_in) {
    int i = blockIdx.x*256 + threadIdx.x;
    if (i < (CIN/2)*CM) {
        int k2 = i >> 6, o = i & 63;
        g_wh[i] = __floats2half2_rn(w_in[o*CIN + 2*k2], w_in[o*CIN + 2*k2 + 1]);
    }
    if (i < B_*CM) g_sums[i] = 0.f;
    if (i == 0) g_maxbits = 0u;
}

// ---------------- conv1x1 in: [B,256,HW] fp32 -> [B,64,HW] fp16 ----------------
__global__ __launch_bounds__(256)
void k_conv_in(const float* __restrict__ x, const float* __restrict__ b_in) {
    int bx = blockIdx.x;
    int b = bx >> 9, tile = bx & 511;
    gemm_body<CIN, false, true>(x + (size_t)b*CIN*HW + tile*128, g_wh, b_in,
                                g_y + (size_t)b*CM*HW + tile*128);
}

// ---------------- fused gaussian(separable) + scharr/laplacian + reductions ----------------
#define TW 64
#define TH 32
__global__ __launch_bounds__(256)
void k_edge() {
    __shared__ float ysh[TH+6][TW+8];
    __shared__ float tsh[TH+6][TW+4];
    __shared__ float smsh[TH+2][TW+4];

    const int t  = threadIdx.x;
    const int x0 = blockIdx.x*TW, y0 = blockIdx.y*TH;
    const int bc = blockIdx.z;
    const __half* __restrict__ yp = g_y    + (size_t)bc*HW;
    __half* __restrict__       ep = g_edge + (size_t)bc*HW;

    for (int i = t; i < (TH+6)*(TW+6); i += 256) {
        int rr = i/(TW+6), cc = i - rr*(TW+6);
        int gr = y0 - 3 + rr, gc = x0 - 3 + cc;
        float v = 0.f;
        if ((unsigned)gr < H_ && (unsigned)gc < W_) v = __half2float(yp[gr*W_ + gc]);
        ysh[rr][cc] = v;
    }
    __syncthreads();

    for (int i = t; i < (TH+6)*(TW+2); i += 256) {
        int rr = i/(TW+2), jj = i - rr*(TW+2);
        tsh[rr][jj] = G0*(ysh[rr][jj] + ysh[rr][jj+4])
                    + G1*(ysh[rr][jj+1] + ysh[rr][jj+3])
                    + G2* ysh[rr][jj+2];
    }
    __syncthreads();

    for (int i = t; i < (TH+2)*(TW+2); i += 256) {
        int ii = i/(TW+2), jj = i - ii*(TW+2);
        int sr = y0 - 1 + ii, sc = x0 - 1 + jj;
        float v = 0.f;
        if ((unsigned)sr < H_ && (unsigned)sc < W_)
            v = G0*(tsh[ii][jj] + tsh[ii+4][jj])
              + G1*(tsh[ii+1][jj] + tsh[ii+3][jj])
              + G2* tsh[ii+2][jj];
        smsh[ii][jj] = v;
    }
    __syncthreads();

    float lsum = 0.f, lmax = 0.f;
    for (int i = t; i < TH*TW; i += 256) {
        int ty = i >> 6, tx = i & 63;
        float a  = smsh[ty  ][tx], bb = smsh[ty  ][tx+1], c2 = smsh[ty  ][tx+2];
        float d  = smsh[ty+1][tx], e  = smsh[ty+1][tx+1], f  = smsh[ty+1][tx+2];
        float g  = smsh[ty+2][tx], h2 = smsh[ty+2][tx+1], i2 = smsh[ty+2][tx+2];
        float g0v  = 3.f*(a - c2) + 10.f*(d  - f ) + 3.f*(g  - i2);
        float g90v = 3.f*(a - g ) + 10.f*(bb - h2) + 3.f*(c2 - i2);
        float lap  = 4.f*e - bb - d - f - h2;
        float edge = fmaxf(fabsf(g0v), fabsf(g90v)) + 0.1f*fabsf(lap);
        ep[(y0+ty)*W_ + x0 + tx] = __float2half(edge);
        lsum += edge;
        lmax = fmaxf(lmax, edge);
    }

#pragma unroll
    for (int off = 16; off; off >>= 1) {
        lsum += __shfl_down_sync(0xffffffffu, lsum, off);
        lmax  = fmaxf(lmax, __shfl_down_sync(0xffffffffu, lmax, off));
    }
    __shared__ float rs[8], rm[8];
    int wid = t >> 5, lane = t & 31;
    if (lane == 0) { rs[wid] = lsum; rm[wid] = lmax; }
    __syncthreads();
    if (t == 0) {
        float s = 0.f, m = 0.f;
#pragma unroll
        for (int wI = 0; wI < 8; ++wI) { s += rs[wI]; m = fmaxf(m, rm[wI]); }
        atomicAdd(&g_sums[bc], s);
        atomicMax(&g_maxbits, __float_as_uint(m));
    }
}

// ---------------- SE MLP: pooled -> scale*inv (tiny, 1 block) ----------------
__global__ void k_se(const float* __restrict__ w_fc1, const float* __restrict__ b_fc1,
                     const float* __restrict__ w_fc2, const float* __restrict__ b_fc2) {
    __shared__ float pooled[B_][CM];
    __shared__ float hsh[B_][4];
    __shared__ float inv_s;
    int t = threadIdx.x;
    if (t == 0) inv_s = 1.f/(__uint_as_float(g_maxbits) + 1e-8f);
    __syncthreads();
    float inv = inv_s;
    if (t < B_*CM)
        pooled[t>>6][t&63] = g_sums[t] * inv * (1.f/(float)HW);
    __syncthreads();
    if (t < B_*4) {
        int b = t >> 2, j = t & 3;
        float z = b_fc1[j];
        for (int c = 0; c < CM; ++c) z += w_fc1[j*CM + c]*pooled[b][c];
        hsh[b][j] = fmaxf(z, 0.f);
    }
    __syncthreads();
    if (t < B_*CM) {
        int b = t >> 6, c = t & 63;
        float z = b_fc2[c];
#pragma unroll
        for (int j = 0; j < 4; ++j) z += w_fc2[c*4 + j]*hsh[b][j];
        g_scale[t] = inv / (1.f + expf(-z));   // sigmoid * inv_max folded
    }
}

// ---------------- fold scale into fp16-paired output weights (parallel) ----------------
__global__ void k_fold(const float* __restrict__ w_out) {
    int i = blockIdx.x*256 + threadIdx.x;    // 32 blocks -> 8192 = B*(CM/2)*CM
    int o = i & 63, k2 = (i >> 6) & 31, b = i >> 11;
    float v0 = w_out[o*CM + 2*k2]     * g_scale[b*CM + 2*k2];
    float v1 = w_out[o*CM + 2*k2 + 1] * g_scale[b*CM + 2*k2 + 1];
    g_oh[i] = __floats2half2_rn(v0, v1);
}

// ---------------- conv1x1 out: [B,64,HW] fp16 -> [B,64,HW] fp32 ----------------
__global__ __launch_bounds__(256)
void k_conv_out(const float* __restrict__ b_out, float* __restrict__ out) {
    int bx = blockIdx.x;
    int b = bx >> 9, tile = bx & 511;
    gemm_body<CM, true, false>(g_edge + (size_t)b*CM*HW + tile*128,
                               g_oh + b*(CM/2)*CM, b_out,
                               out + (size_t)b*CM*HW + tile*128);
}

// ---------------- launch ----------------
extern "C" void kernel_launch(void* const* d_in, const int* in_sizes, int n_in,
                              void* d_out, int out_size) {
    const float* x     = (const float*)d_in[0];
    const float* w_in  = (const float*)d_in[1];
    const float* b_in  = (const float*)d_in[2];
    const float* w_fc1 = (const float*)d_in[3];
    const float* b_fc1 = (const float*)d_in[4];
    const float* w_fc2 = (const float*)d_in[5];
    const float* b_fc2 = (const float*)d_in[6];
    const float* w_out = (const float*)d_in[7];
    const float* b_out = (const float*)d_in[8];
    float* out = (float*)d_out;

    k_init<<<64, 256>>>(w_in);
    k_conv_in<<<B_*(HW/128), 256>>>(x, b_in);
    k_edge<<<dim3(W_/TW, H_/TH, B_*CM), 256>>>();
    k_se<<<1, 256>>>(w_fc1, b_fc1, w_fc2, b_fc2);
    k_fold<<<32, 256>>>(w_out);
    k_conv_out<<<B_*(HW/128), 256>>>(b_out, out);
}